// round 12
// baseline (speedup 1.0000x reference)
#include <cuda_runtime.h>
#include <cuda_fp16.h>
#include <cstdint>

#define Bb 512
#define Tt 512
#define Ff 32
#define Hh 128
#define Ee 64
#define KPAD 200
#define KPG  136     // pregemm2 B row (128 + 8 pad)
#define KP2  72      // lstm2r B row (64 + 8 pad)

__device__ uint32_t g_seq1[(size_t)Tt*Bb*Hh];    // layer-1 h packed (hi|lo<<16) fp16
__device__ float4   g_xg2[(size_t)Tt*Bb*Ee];     // W_ih2·h1 gates (i,f,g,o) per (t,b,u)

// ---------------- helpers ----------------
__device__ __forceinline__ uint32_t smem_u32(const void* p) {
    uint32_t a;
    asm("{ .reg .u64 t; cvta.to.shared.u64 t, %1; cvt.u32.u64 %0, t; }" : "=r"(a) : "l"(p));
    return a;
}
__device__ __forceinline__ void mma16816(float* d, const uint32_t* a, uint32_t b0, uint32_t b1) {
    asm("mma.sync.aligned.m16n8k16.row.col.f32.f16.f16.f32 "
        "{%0,%1,%2,%3}, {%4,%5,%6,%7}, {%8,%9}, {%0,%1,%2,%3};"
        : "+f"(d[0]), "+f"(d[1]), "+f"(d[2]), "+f"(d[3])
        : "r"(a[0]), "r"(a[1]), "r"(a[2]), "r"(a[3]), "r"(b0), "r"(b1));
}
__device__ __forceinline__ void splith(float v, __half& hi, __half& lo) {
    hi = __float2half_rn(v);
    lo = __float2half_rn(v - __half2float(hi));
}
__device__ __forceinline__ uint32_t pkh(__half a, __half b) {
    return (uint32_t)__half_as_ushort(a) | ((uint32_t)__half_as_ushort(b) << 16);
}
__device__ __forceinline__ void mbar_init(void* m, uint32_t cnt) {
    asm volatile("mbarrier.init.shared.b64 [%0], %1;" :: "r"(smem_u32(m)), "r"(cnt) : "memory");
}
__device__ __forceinline__ void mbar_wait(void* m, uint32_t parity) {
    uint32_t a = smem_u32(m), done;
    do {
        asm volatile("{\n\t.reg .pred p;\n\t"
            "mbarrier.try_wait.parity.acquire.cluster.shared::cta.b64 p, [%1], %2, 0x989680;\n\t"
            "selp.b32 %0, 1, 0, p;\n\t}" : "=r"(done) : "r"(a), "r"(parity) : "memory");
    } while (!done);
}
__device__ __forceinline__ uint32_t mapa_u32(uint32_t saddr, uint32_t peer) {
    uint32_t r;
    asm("mapa.shared::cluster.u32 %0, %1, %2;" : "=r"(r) : "r"(saddr), "r"(peer));
    return r;
}
#define CLU_SYNC() do { asm volatile("barrier.cluster.arrive.aligned;" ::: "memory"); \
                        asm volatile("barrier.cluster.wait.aligned;" ::: "memory"); } while (0)

__device__ __forceinline__ float sigm(float z) { return __fdividef(1.0f, 1.0f + __expf(-z)); }
__device__ __forceinline__ float tanh_(float z) {
    float e = __expf(2.0f * z);
    return 1.0f - __fdividef(2.0f, e + 1.0f);
}

// ---------------------------------------------------------------------------
// Layer 1 (identical to R11): 64 clusters x 2 CTAs x 512 threads.
// ---------------------------------------------------------------------------
__global__ void __launch_bounds__(512, 1) __cluster_dims__(2, 1, 1)
lstm1_mma(const float* __restrict__ x,
          const float* __restrict__ Wih, const float* __restrict__ Whh,
          const float* __restrict__ bih, const float* __restrict__ bhh)
{
    __shared__ __half Bhi[2][8][KPAD];
    __shared__ __half Blo[2][8][KPAD];
    __shared__ alignas(8) unsigned long long mbar[2];

    const int tid = threadIdx.x;
    uint32_t rank;
    asm("mov.u32 %0, %%cluster_ctarank;" : "=r"(rank));
    const int r0 = (blockIdx.x >> 1) * 8;
    const int U0 = (int)rank * 64;
    const int lane = tid & 31, warp = tid >> 5;
    const int tg = lane & 3, gid = lane >> 2;
    const int q = gid >> 2, m = gid & 3;
    const int kf_own = (int)rank * 4;
    const int kf_peer = 4 - kf_own;

    for (int i = tid; i < 2 * 8 * KPAD; i += 512) {
        (&Bhi[0][0][0])[i] = __ushort_as_half(0);
        (&Blo[0][0][0])[i] = __ushort_as_half(0);
    }

    uint32_t Ahi[10][4], Alo[10][4];
#pragma unroll
    for (int kf = 0; kf < 10; kf++) {
        int k0 = kf * 16 + tg * 2;
#pragma unroll
        for (int qq = 0; qq < 4; qq++) {
            int rslot = gid + (qq & 1) * 8;
            int kk = k0 + (qq >> 1) * 8;
            int ul = warp * 4 + (rslot & 3);
            int gate = 2 * (rslot >> 3) + ((rslot >> 2) & 1);
            int R = gate * Hh + U0 + ul;
            float w0 = (kk < Hh) ? Whh[R * Hh + kk] : Wih[R * Ff + (kk - Hh)];
            float w1 = (kk + 1 < Hh) ? Whh[R * Hh + kk + 1] : Wih[R * Ff + (kk + 1 - Hh)];
            __half h0, l0, h1, l1;
            splith(w0, h0, l0);
            splith(w1, h1, l1);
            Ahi[kf][qq] = pkh(h0, h1);
            Alo[kf][qq] = pkh(l0, l1);
        }
    }

    const int u = U0 + warp * 4 + m;
    const int c = tg * 2 + q;
    const float bi_ = bih[u] + bhh[u];
    const float bf_ = bih[Hh + u] + bhh[Hh + u];
    const float bg_ = bih[2 * Hh + u] + bhh[2 * Hh + u];
    const float bo_ = bih[3 * Hh + u] + bhh[3 * Hh + u];

    if (tid == 0) { mbar_init(&mbar[0], 32); mbar_init(&mbar[1], 32); }
    __syncthreads();

    uint32_t cp_lhi = 0, cp_llo = 0, cp_rhi = 0, cp_rlo = 0, rmb = 0;
    if (tid < 32) {
        uint32_t off = (uint32_t)(((tid >> 3) & 3) * (KPAD * 2) + U0 * 2 + (tid & 7) * 16);
        cp_lhi = smem_u32(&Bhi[0][0][0]) + off;
        cp_llo = smem_u32(&Blo[0][0][0]) + off;
        cp_rhi = mapa_u32(cp_lhi, rank ^ 1u);
        cp_rlo = mapa_u32(cp_llo, rank ^ 1u);
        rmb    = mapa_u32(smem_u32(&mbar[0]), rank ^ 1u);
    }

    const int xb = tid >> 5, xf = tid & 31;
    float xn = 0.0f;
    if (tid < 256) {
        float x0 = x[((size_t)(r0 + xb) * Tt + 0) * Ff + xf];
        __half xh, xl;
        splith(x0, xh, xl);
        Bhi[0][xb][Hh + xf] = xh;
        Blo[0][xb][Hh + xf] = xl;
        xn = x[((size_t)(r0 + xb) * Tt + 1) * Ff + xf];
    }
    __syncthreads();
    CLU_SYNC();

    float cst = 0.0f;
    int ph0 = 0, ph1 = 0;
    const int boffw = gid * KPAD + tg * 2;

    for (int t = 0; t < Tt; t++) {
        const int cur = t & 1;

        float dh[4] = {0.f,0.f,0.f,0.f}, dm[4] = {0.f,0.f,0.f,0.f}, dl[4] = {0.f,0.f,0.f,0.f};
        const __half* bh = &Bhi[cur][0][0];
        const __half* bl = &Blo[cur][0][0];

#pragma unroll
        for (int i = 0; i < 6; i++) {
            const int kf = (i < 4) ? (kf_own + i) : (8 + (i - 4));
            uint32_t b0 = *(const uint32_t*)(bh + boffw + kf * 16);
            uint32_t b1 = *(const uint32_t*)(bh + boffw + kf * 16 + 8);
            uint32_t c0 = *(const uint32_t*)(bl + boffw + kf * 16);
            uint32_t c1 = *(const uint32_t*)(bl + boffw + kf * 16 + 8);
            mma16816(dh, Ahi[kf], b0, b1);
            mma16816(dm, Alo[kf], b0, b1);
            mma16816(dl, Ahi[kf], c0, c1);
        }

        if (t > 0) {
            if (cur == 0) { mbar_wait(&mbar[0], (uint32_t)ph0); ph0 ^= 1; }
            else          { mbar_wait(&mbar[1], (uint32_t)ph1); ph1 ^= 1; }
        }
#pragma unroll
        for (int i = 0; i < 4; i++) {
            const int kf = kf_peer + i;
            uint32_t b0 = *(const uint32_t*)(bh + boffw + kf * 16);
            uint32_t b1 = *(const uint32_t*)(bh + boffw + kf * 16 + 8);
            uint32_t c0 = *(const uint32_t*)(bl + boffw + kf * 16);
            uint32_t c1 = *(const uint32_t*)(bl + boffw + kf * 16 + 8);
            mma16816(dh, Ahi[kf], b0, b1);
            mma16816(dm, Alo[kf], b0, b1);
            mma16816(dl, Ahi[kf], c0, c1);
        }

        float d0 = dh[0] + dm[0] + dl[0];
        float d1 = dh[1] + dm[1] + dl[1];
        float d2 = dh[2] + dm[2] + dl[2];
        float d3 = dh[3] + dm[3] + dl[3];

        float X = __shfl_xor_sync(0xFFFFFFFFu, q ? d0 : d1, 16);
        float Y = __shfl_xor_sync(0xFFFFFFFFu, q ? d2 : d3, 16);
        float zi = (q ? X : d0) + bi_;
        float zf = (q ? d1 : X) + bf_;
        float zg = (q ? Y : d2) + bg_;
        float zo = (q ? d3 : Y) + bo_;

        cst = sigm(zf) * cst + sigm(zi) * tanh_(zg);
        float h = sigm(zo) * tanh_(cst);
        __half hh, hl;
        splith(h, hh, hl);
        g_seq1[((size_t)t * Bb + r0 + c) * Hh + u] = pkh(hh, hl);

        const int nb = cur ^ 1;
        if (t + 1 < Tt) {
            Bhi[nb][c][u] = hh;
            Blo[nb][c][u] = hl;
            if (tid < 256) {
                __half xh, xl;
                splith(xn, xh, xl);
                Bhi[nb][xb][Hh + xf] = xh;
                Blo[nb][xb][Hh + xf] = xl;
                xn = (t + 2 < Tt) ? x[((size_t)(r0 + xb) * Tt + t + 2) * Ff + xf] : 0.0f;
            }
        }
        __syncthreads();

        if (t + 1 < Tt && tid < 32) {
            const uint32_t bo_ofs = (uint32_t)nb * (uint32_t)(8 * KPAD * 2);
#pragma unroll
            for (int i = 0; i < 4; i++) {
                uint32_t la = ((i >> 1) ? cp_llo : cp_lhi) + bo_ofs + (uint32_t)((i & 1) * 4 * KPAD * 2);
                uint32_t ra = ((i >> 1) ? cp_rlo : cp_rhi) + bo_ofs + (uint32_t)((i & 1) * 4 * KPAD * 2);
                uint32_t v0, v1, v2, v3;
                asm volatile("ld.shared.v4.u32 {%0,%1,%2,%3}, [%4];"
                    : "=r"(v0), "=r"(v1), "=r"(v2), "=r"(v3) : "r"(la));
                unsigned long long p0, p1;
                asm("mov.b64 %0, {%1, %2};" : "=l"(p0) : "r"(v0), "r"(v1));
                asm("mov.b64 %0, {%1, %2};" : "=l"(p1) : "r"(v2), "r"(v3));
                asm volatile("st.shared::cluster.b64 [%0], %1;" :: "r"(ra), "l"(p0) : "memory");
                asm volatile("st.shared::cluster.b64 [%0], %1;" :: "r"(ra + 8), "l"(p1) : "memory");
            }
            asm volatile("mbarrier.arrive.release.cluster.shared::cluster.b64 _, [%0];"
                :: "r"(rmb + (uint32_t)nb * 8) : "memory");
        }
    }
    CLU_SYNC();
}

// ---------------------------------------------------------------------------
// pregemm2: xg2[t][b][u] = (i,f,g,o) partial gates from W_ih2 · h1[t][b].
// 128 CTAs: (b-group = bid>>1, t-half = bid&1 -> 256 steps). No recurrence:
// double-buffered B, prefetch t+1 while MMA(t). Same 3-term hi/lo math and
// the same warp/lane->cell mapping as the recurrent kernel.
// ---------------------------------------------------------------------------
__global__ void __launch_bounds__(512, 1)
pregemm2(const float* __restrict__ Wih)
{
    __shared__ __half Bhi[2][8][KPG];
    __shared__ __half Blo[2][8][KPG];

    const int tid = threadIdx.x;
    const int lane = tid & 31, warp = tid >> 5;
    const int tg = lane & 3, gid = lane >> 2;
    const int q = gid >> 2, m = gid & 3;
    const int r0 = (blockIdx.x >> 1) * 8;
    const int t0 = (blockIdx.x & 1) * 256;

    uint32_t Ahi[8][4], Alo[8][4];
#pragma unroll
    for (int kf = 0; kf < 8; kf++) {
        int k0 = kf * 16 + tg * 2;
#pragma unroll
        for (int qq = 0; qq < 4; qq++) {
            int rslot = gid + (qq & 1) * 8;
            int kk = k0 + (qq >> 1) * 8;
            int ul = warp * 4 + (rslot & 3);
            int gate = 2 * (rslot >> 3) + ((rslot >> 2) & 1);
            int R = gate * Ee + ul;
            float w0 = Wih[R * Hh + kk];
            float w1 = Wih[R * Hh + kk + 1];
            __half h0, l0, h1, l1;
            splith(w0, h0, l0);
            splith(w1, h1, l1);
            Ahi[kf][qq] = pkh(h0, h1);
            Alo[kf][qq] = pkh(l0, l1);
        }
    }

    const int u = warp * 4 + m;
    const int c = tg * 2 + q;
    const int lk = tid & 127, lb = tid >> 7;

    // load t0 into buf 0, prefetch t0+1
    uint32_t p0 = g_seq1[((size_t)t0 * Bb + r0 + lb) * Hh + lk];
    uint32_t p1 = g_seq1[((size_t)t0 * Bb + r0 + lb + 4) * Hh + lk];
    Bhi[0][lb][lk]     = __ushort_as_half((uint16_t)(p0 & 0xFFFF));
    Blo[0][lb][lk]     = __ushort_as_half((uint16_t)(p0 >> 16));
    Bhi[0][lb + 4][lk] = __ushort_as_half((uint16_t)(p1 & 0xFFFF));
    Blo[0][lb + 4][lk] = __ushort_as_half((uint16_t)(p1 >> 16));
    p0 = g_seq1[((size_t)(t0 + 1) * Bb + r0 + lb) * Hh + lk];
    p1 = g_seq1[((size_t)(t0 + 1) * Bb + r0 + lb + 4) * Hh + lk];
    __syncthreads();

    const int boffw = gid * KPG + tg * 2;

    for (int tt = 0; tt < 256; tt++) {
        const int t = t0 + tt;
        const int cur = tt & 1, nb = cur ^ 1;

        float dh[4] = {0.f,0.f,0.f,0.f}, dm[4] = {0.f,0.f,0.f,0.f}, dl[4] = {0.f,0.f,0.f,0.f};
        const __half* bh = &Bhi[cur][0][0];
        const __half* bl = &Blo[cur][0][0];
#pragma unroll
        for (int kf = 0; kf < 8; kf++) {
            uint32_t b0 = *(const uint32_t*)(bh + boffw + kf * 16);
            uint32_t b1 = *(const uint32_t*)(bh + boffw + kf * 16 + 8);
            uint32_t c0 = *(const uint32_t*)(bl + boffw + kf * 16);
            uint32_t c1 = *(const uint32_t*)(bl + boffw + kf * 16 + 8);
            mma16816(dh, Ahi[kf], b0, b1);
            mma16816(dm, Alo[kf], b0, b1);
            mma16816(dl, Ahi[kf], c0, c1);
        }

        if (tt + 1 < 256) {
            Bhi[nb][lb][lk]     = __ushort_as_half((uint16_t)(p0 & 0xFFFF));
            Blo[nb][lb][lk]     = __ushort_as_half((uint16_t)(p0 >> 16));
            Bhi[nb][lb + 4][lk] = __ushort_as_half((uint16_t)(p1 & 0xFFFF));
            Blo[nb][lb + 4][lk] = __ushort_as_half((uint16_t)(p1 >> 16));
            if (tt + 2 < 256) {
                p0 = g_seq1[((size_t)(t + 2) * Bb + r0 + lb) * Hh + lk];
                p1 = g_seq1[((size_t)(t + 2) * Bb + r0 + lb + 4) * Hh + lk];
            }
        }

        float d0 = dh[0] + dm[0] + dl[0];
        float d1 = dh[1] + dm[1] + dl[1];
        float d2 = dh[2] + dm[2] + dl[2];
        float d3 = dh[3] + dm[3] + dl[3];

        float X = __shfl_xor_sync(0xFFFFFFFFu, q ? d0 : d1, 16);
        float Y = __shfl_xor_sync(0xFFFFFFFFu, q ? d2 : d3, 16);
        float zi = q ? X : d0;
        float zf = q ? d1 : X;
        float zg = q ? Y : d2;
        float zo = q ? d3 : Y;

        g_xg2[((size_t)t * Bb + r0 + c) * Ee + u] = make_float4(zi, zf, zg, zo);
        __syncthreads();
    }
}

// ---------------------------------------------------------------------------
// lstm2r: recurrent part only (K=64 over h2). 64 blocks x 512 threads.
// Gates = xg2 (prefetched float4) + W_hh2·h2 (12 HMMA/warp) + biases.
// ---------------------------------------------------------------------------
__global__ void __launch_bounds__(512, 1)
lstm2r(const float* __restrict__ Whh,
       const float* __restrict__ bih, const float* __restrict__ bhh,
       float* __restrict__ out)
{
    __shared__ __half Bhi[2][8][KP2];
    __shared__ __half Blo[2][8][KP2];

    const int tid = threadIdx.x;
    const int r0 = blockIdx.x * 8;
    const int lane = tid & 31, warp = tid >> 5;
    const int tg = lane & 3, gid = lane >> 2;
    const int q = gid >> 2, m = gid & 3;

    for (int i = tid; i < 2 * 8 * KP2; i += 512) {
        (&Bhi[0][0][0])[i] = __ushort_as_half(0);
        (&Blo[0][0][0])[i] = __ushort_as_half(0);
    }

    uint32_t Ahi[4][4], Alo[4][4];
#pragma unroll
    for (int kf = 0; kf < 4; kf++) {
        int k0 = kf * 16 + tg * 2;
#pragma unroll
        for (int qq = 0; qq < 4; qq++) {
            int rslot = gid + (qq & 1) * 8;
            int kk = k0 + (qq >> 1) * 8;
            int ul = warp * 4 + (rslot & 3);
            int gate = 2 * (rslot >> 3) + ((rslot >> 2) & 1);
            int R = gate * Ee + ul;
            float w0 = Whh[R * Ee + kk];
            float w1 = Whh[R * Ee + kk + 1];
            __half h0, l0, h1, l1;
            splith(w0, h0, l0);
            splith(w1, h1, l1);
            Ahi[kf][qq] = pkh(h0, h1);
            Alo[kf][qq] = pkh(l0, l1);
        }
    }

    const int u = warp * 4 + m;
    const int c = tg * 2 + q;
    const float bi_ = bih[u] + bhh[u];
    const float bf_ = bih[Ee + u] + bhh[Ee + u];
    const float bg_ = bih[2 * Ee + u] + bhh[2 * Ee + u];
    const float bo_ = bih[3 * Ee + u] + bhh[3 * Ee + u];

    float4 xg = g_xg2[((size_t)0 * Bb + r0 + c) * Ee + u];
    __syncthreads();

    float cst = 0.0f, hlast = 0.0f;
    const int boffw = gid * KP2 + tg * 2;

    for (int t = 0; t < Tt; t++) {
        const int cur = t & 1;
        float dh[4] = {0.f,0.f,0.f,0.f}, dm[4] = {0.f,0.f,0.f,0.f}, dl[4] = {0.f,0.f,0.f,0.f};
        const __half* bh = &Bhi[cur][0][0];
        const __half* bl = &Blo[cur][0][0];
#pragma unroll
        for (int kf = 0; kf < 4; kf++) {
            uint32_t b0 = *(const uint32_t*)(bh + boffw + kf * 16);
            uint32_t b1 = *(const uint32_t*)(bh + boffw + kf * 16 + 8);
            uint32_t c0 = *(const uint32_t*)(bl + boffw + kf * 16);
            uint32_t c1 = *(const uint32_t*)(bl + boffw + kf * 16 + 8);
            mma16816(dh, Ahi[kf], b0, b1);
            mma16816(dm, Alo[kf], b0, b1);
            mma16816(dl, Ahi[kf], c0, c1);
        }
        float d0 = dh[0] + dm[0] + dl[0];
        float d1 = dh[1] + dm[1] + dl[1];
        float d2 = dh[2] + dm[2] + dl[2];
        float d3 = dh[3] + dm[3] + dl[3];

        float X = __shfl_xor_sync(0xFFFFFFFFu, q ? d0 : d1, 16);
        float Y = __shfl_xor_sync(0xFFFFFFFFu, q ? d2 : d3, 16);
        float zi = (q ? X : d0) + bi_ + xg.x;
        float zf = (q ? d1 : X) + bf_ + xg.y;
        float zg = (q ? Y : d2) + bg_ + xg.z;
        float zo = (q ? d3 : Y) + bo_ + xg.w;

        // prefetch next step's xg2 (off the MUFU critical path)
        if (t + 1 < Tt) xg = g_xg2[((size_t)(t + 1) * Bb + r0 + c) * Ee + u];

        cst = sigm(zf) * cst + sigm(zi) * tanh_(zg);
        hlast = sigm(zo) * tanh_(cst);

        if (t + 1 < Tt) {
            const int nb = cur ^ 1;
            __half hh, hl;
            splith(hlast, hh, hl);
            Bhi[nb][c][u] = hh;
            Blo[nb][c][u] = hl;
        }
        __syncthreads();
    }
    out[(size_t)(r0 + c) * Ee + u] = hlast;
}

extern "C" void kernel_launch(void* const* d_in, const int* in_sizes, int n_in,
                              void* d_out, int out_size)
{
    const float* x    = (const float*)d_in[0];
    const float* Wih1 = (const float*)d_in[1];
    const float* Whh1 = (const float*)d_in[2];
    const float* bih1 = (const float*)d_in[3];
    const float* bhh1 = (const float*)d_in[4];
    const float* Wih2 = (const float*)d_in[5];
    const float* Whh2 = (const float*)d_in[6];
    const float* bih2 = (const float*)d_in[7];
    const float* bhh2 = (const float*)d_in[8];
    float* out = (float*)d_out;

    lstm1_mma<<<128, 512>>>(x, Wih1, Whh1, bih1, bhh1);
    pregemm2<<<128, 512>>>(Wih2);
    lstm2r<<<64, 512>>>(Whh2, bih2, bhh2, out);
}

// round 13
// speedup vs baseline: 1.0980x; 1.0980x over previous
#include <cuda_runtime.h>
#include <cuda_fp16.h>
#include <cstdint>

#define Bb 512
#define Tt 512
#define Ff 32
#define Hh 128
#define Ee 64
#define NKF1 10            // lstm1 K-frags (K=160)
#define NKF2 12            // lstm2 K-frags (K=192)
#define BUF1 (NKF1*32)     // uint4s per buffer, lstm1 (5120 B)
#define BUF2 (NKF2*32)     // uint4s per buffer, lstm2 (6144 B)

__device__ uint32_t g_seq1[(size_t)Tt*Bb*Hh];   // layer-1 h packed (hi | lo<<16) fp16

// ---------------- helpers ----------------
__device__ __forceinline__ uint32_t smem_u32(const void* p) {
    uint32_t a;
    asm("{ .reg .u64 t; cvta.to.shared.u64 t, %1; cvt.u32.u64 %0, t; }" : "=r"(a) : "l"(p));
    return a;
}
__device__ __forceinline__ void mma16816(float* d, const uint32_t* a, uint32_t b0, uint32_t b1) {
    asm("mma.sync.aligned.m16n8k16.row.col.f32.f16.f16.f32 "
        "{%0,%1,%2,%3}, {%4,%5,%6,%7}, {%8,%9}, {%0,%1,%2,%3};"
        : "+f"(d[0]), "+f"(d[1]), "+f"(d[2]), "+f"(d[3])
        : "r"(a[0]), "r"(a[1]), "r"(a[2]), "r"(a[3]), "r"(b0), "r"(b1));
}
__device__ __forceinline__ void splith(float v, __half& hi, __half& lo) {
    hi = __float2half_rn(v);
    lo = __float2half_rn(v - __half2float(hi));
}
__device__ __forceinline__ uint32_t pkh(__half a, __half b) {
    return (uint32_t)__half_as_ushort(a) | ((uint32_t)__half_as_ushort(b) << 16);
}
// byte offset of value (n, k) inside a fragment-packed buffer.
// uint4 @ ((kf*8+n)*4+tg)*16 = {hi(k0,k0+1), hi(k0+8,k0+9), lo(k0,k0+1), lo(k0+8,k0+9)}
// hi at w*4 + hp*2; lo at +8.
__device__ __forceinline__ int bf_off(int n, int k) {
    int kf = k >> 4, r = k & 15;
    return ((kf * 8 + n) * 4 + ((r & 7) >> 1)) * 16 + (r >> 3) * 4 + (r & 1) * 2;
}
__device__ __forceinline__ void mbar_init(void* m, uint32_t cnt) {
    asm volatile("mbarrier.init.shared.b64 [%0], %1;" :: "r"(smem_u32(m)), "r"(cnt) : "memory");
}
__device__ __forceinline__ void mbar_wait(void* m, uint32_t parity) {
    uint32_t a = smem_u32(m), done;
    do {
        asm volatile("{\n\t.reg .pred p;\n\t"
            "mbarrier.try_wait.parity.acquire.cluster.shared::cta.b64 p, [%1], %2, 0x989680;\n\t"
            "selp.b32 %0, 1, 0, p;\n\t}" : "=r"(done) : "r"(a), "r"(parity) : "memory");
    } while (!done);
}
__device__ __forceinline__ uint32_t mapa_u32(uint32_t saddr, uint32_t peer) {
    uint32_t r;
    asm("mapa.shared::cluster.u32 %0, %1, %2;" : "=r"(r) : "r"(saddr), "r"(peer));
    return r;
}
#define CLU_SYNC() do { asm volatile("barrier.cluster.arrive.aligned;" ::: "memory"); \
                        asm volatile("barrier.cluster.wait.aligned;" ::: "memory"); } while (0)

__device__ __forceinline__ float sigm(float z) { return __fdividef(1.0f, 1.0f + __expf(-z)); }
__device__ __forceinline__ float tanh_(float z) {
    float e = __expf(2.0f * z);
    return 1.0f - __fdividef(2.0f, e + 1.0f);
}

// ---------------------------------------------------------------------------
// Layer 1: 64 clusters x 2 CTAs x 512 threads (R11 structure, frag-packed B).
// CTA rank owns units U0..U0+63. K: 0..127 h (kf 0..7), 128..159 x (kf 8,9).
// ---------------------------------------------------------------------------
__global__ void __launch_bounds__(512, 1) __cluster_dims__(2, 1, 1)
lstm1_mma(const float* __restrict__ x,
          const float* __restrict__ Wih, const float* __restrict__ Whh,
          const float* __restrict__ bih, const float* __restrict__ bhh)
{
    __shared__ uint4 BF[2][BUF1];
    __shared__ alignas(8) unsigned long long mbar[2];

    const int tid = threadIdx.x;
    uint32_t rank;
    asm("mov.u32 %0, %%cluster_ctarank;" : "=r"(rank));
    const int r0 = (blockIdx.x >> 1) * 8;
    const int U0 = (int)rank * 64;
    const int lane = tid & 31, warp = tid >> 5;
    const int tg = lane & 3, gid = lane >> 2;
    const int q = gid >> 2, m = gid & 3;
    const int kf_own = (int)rank * 4;
    const int kf_peer = 4 - kf_own;

    for (int i = tid; i < 2 * BUF1; i += 512)
        ((uint4*)BF)[i] = make_uint4(0, 0, 0, 0);

    uint32_t Ahi[10][4], Alo[10][4];
#pragma unroll
    for (int kf = 0; kf < 10; kf++) {
        int k0 = kf * 16 + tg * 2;
#pragma unroll
        for (int qq = 0; qq < 4; qq++) {
            int rslot = gid + (qq & 1) * 8;
            int kk = k0 + (qq >> 1) * 8;
            int ul = warp * 4 + (rslot & 3);
            int gate = 2 * (rslot >> 3) + ((rslot >> 2) & 1);
            int R = gate * Hh + U0 + ul;
            float w0 = (kk < Hh) ? Whh[R * Hh + kk] : Wih[R * Ff + (kk - Hh)];
            float w1 = (kk + 1 < Hh) ? Whh[R * Hh + kk + 1] : Wih[R * Ff + (kk + 1 - Hh)];
            __half h0, l0, h1, l1;
            splith(w0, h0, l0);
            splith(w1, h1, l1);
            Ahi[kf][qq] = pkh(h0, h1);
            Alo[kf][qq] = pkh(l0, l1);
        }
    }

    const int u = U0 + warp * 4 + m;
    const int c = tg * 2 + q;
    const float bi_ = bih[u] + bhh[u];
    const float bf_ = bih[Hh + u] + bhh[Hh + u];
    const float bg_ = bih[2 * Hh + u] + bhh[2 * Hh + u];
    const float bo_ = bih[3 * Hh + u] + bhh[3 * Hh + u];

    if (tid == 0) { mbar_init(&mbar[0], 32); mbar_init(&mbar[1], 32); }
    __syncthreads();

    // copy warp: own kf region = 4 kf x 512B = 2KB contiguous at rank*2048
    uint32_t cp_l = 0, cp_r = 0, rmb = 0;
    if (tid < 32) {
        cp_l = smem_u32(&BF[0][0]) + rank * 2048u + (uint32_t)tid * 16u;
        cp_r = mapa_u32(cp_l, rank ^ 1u);
        rmb  = mapa_u32(smem_u32(&mbar[0]), rank ^ 1u);
    }

    // per-thread precomputed fill offsets
    char* bfb = (char*)&BF[0][0];
    const int cellOff = bf_off(c, u);                    // own h cell
    const int xb = tid >> 5, xf = tid & 31;
    const int xOff = bf_off(xb, Hh + xf);                // x loader (tid<256)

    float xn = 0.0f;
    if (tid < 256) {
        float x0 = x[((size_t)(r0 + xb) * Tt + 0) * Ff + xf];
        __half xh, xl;
        splith(x0, xh, xl);
        *(__half*)(bfb + xOff) = xh;
        *(__half*)(bfb + xOff + 8) = xl;
        xn = x[((size_t)(r0 + xb) * Tt + 1) * Ff + xf];
    }
    __syncthreads();
    CLU_SYNC();

    float cst = 0.0f;
    int ph0 = 0, ph1 = 0;
    const uint4* bfq = &BF[0][0] + (gid * 4 + tg);       // + kf*32 per frag

    for (int t = 0; t < Tt; t++) {
        const int cur = t & 1;
        const uint4* bv = bfq + cur * BUF1;

        float dh[4] = {0.f,0.f,0.f,0.f}, dm[4] = {0.f,0.f,0.f,0.f}, dl[4] = {0.f,0.f,0.f,0.f};

        // local K-frags first: own units (4) + x (2)
#pragma unroll
        for (int i = 0; i < 6; i++) {
            const int kf = (i < 4) ? (kf_own + i) : (8 + (i - 4));
            uint4 v = bv[kf * 32];
            mma16816(dh, Ahi[kf], v.x, v.y);
            mma16816(dm, Alo[kf], v.x, v.y);
            mma16816(dl, Ahi[kf], v.z, v.w);
        }

        if (t > 0) {
            if (cur == 0) { mbar_wait(&mbar[0], (uint32_t)ph0); ph0 ^= 1; }
            else          { mbar_wait(&mbar[1], (uint32_t)ph1); ph1 ^= 1; }
        }
#pragma unroll
        for (int i = 0; i < 4; i++) {
            const int kf = kf_peer + i;
            uint4 v = bv[kf * 32];
            mma16816(dh, Ahi[kf], v.x, v.y);
            mma16816(dm, Alo[kf], v.x, v.y);
            mma16816(dl, Ahi[kf], v.z, v.w);
        }

        float d0 = dh[0] + dm[0] + dl[0];
        float d1 = dh[1] + dm[1] + dl[1];
        float d2 = dh[2] + dm[2] + dl[2];
        float d3 = dh[3] + dm[3] + dl[3];

        float X = __shfl_xor_sync(0xFFFFFFFFu, q ? d0 : d1, 16);
        float Y = __shfl_xor_sync(0xFFFFFFFFu, q ? d2 : d3, 16);
        float zi = (q ? X : d0) + bi_;
        float zf = (q ? d1 : X) + bf_;
        float zg = (q ? Y : d2) + bg_;
        float zo = (q ? d3 : Y) + bo_;

        cst = sigm(zf) * cst + sigm(zi) * tanh_(zg);
        float h = sigm(zo) * tanh_(cst);
        __half hh, hl;
        splith(h, hh, hl);
        g_seq1[((size_t)t * Bb + r0 + c) * Hh + u] = pkh(hh, hl);

        const int nb = cur ^ 1;
        if (t + 1 < Tt) {
            char* dst = bfb + nb * (int)sizeof(uint4) * BUF1;
            *(__half*)(dst + cellOff) = hh;
            *(__half*)(dst + cellOff + 8) = hl;
            if (tid < 256) {
                __half xh, xl;
                splith(xn, xh, xl);
                *(__half*)(dst + xOff) = xh;
                *(__half*)(dst + xOff + 8) = xl;
                xn = (t + 2 < Tt) ? x[((size_t)(r0 + xb) * Tt + t + 2) * Ff + xf] : 0.0f;
            }
        }
        __syncthreads();

        if (t + 1 < Tt && tid < 32) {
            const uint32_t bofs = (uint32_t)nb * (uint32_t)(sizeof(uint4) * BUF1);
#pragma unroll
            for (int j = 0; j < 4; j++) {
                uint32_t la = cp_l + bofs + (uint32_t)j * 512u;
                uint32_t ra = cp_r + bofs + (uint32_t)j * 512u;
                uint32_t v0, v1, v2, v3;
                asm volatile("ld.shared.v4.u32 {%0,%1,%2,%3}, [%4];"
                    : "=r"(v0), "=r"(v1), "=r"(v2), "=r"(v3) : "r"(la));
                unsigned long long p0, p1;
                asm("mov.b64 %0, {%1, %2};" : "=l"(p0) : "r"(v0), "r"(v1));
                asm("mov.b64 %0, {%1, %2};" : "=l"(p1) : "r"(v2), "r"(v3));
                asm volatile("st.shared::cluster.b64 [%0], %1;" :: "r"(ra), "l"(p0) : "memory");
                asm volatile("st.shared::cluster.b64 [%0], %1;" :: "r"(ra + 8), "l"(p1) : "memory");
            }
            asm volatile("mbarrier.arrive.release.cluster.shared::cluster.b64 _, [%0];"
                :: "r"(rmb + (uint32_t)nb * 8) : "memory");
        }
    }
    CLU_SYNC();
}

// ---------------------------------------------------------------------------
// Layer 2: 64 blocks x 512 threads (R11 structure, frag-packed B).
// K: 0..127 h1 (kf 0..7), 128..191 h2 (kf 8..11).
// ---------------------------------------------------------------------------
__global__ void __launch_bounds__(512, 1)
lstm2_mma(const float* __restrict__ Wih, const float* __restrict__ Whh,
          const float* __restrict__ bih, const float* __restrict__ bhh,
          float* __restrict__ out)
{
    __shared__ uint4 BF[2][BUF2];

    const int tid = threadIdx.x;
    const int r0 = blockIdx.x * 8;
    const int lane = tid & 31, warp = tid >> 5;
    const int tg = lane & 3, gid = lane >> 2;
    const int q = gid >> 2, m = gid & 3;

    for (int i = tid; i < 2 * BUF2; i += 512)
        ((uint4*)BF)[i] = make_uint4(0, 0, 0, 0);

    uint32_t Ahi[12][4], Alo[12][4];
#pragma unroll
    for (int kf = 0; kf < 12; kf++) {
        int k0 = kf * 16 + tg * 2;
#pragma unroll
        for (int qq = 0; qq < 4; qq++) {
            int rslot = gid + (qq & 1) * 8;
            int kk = k0 + (qq >> 1) * 8;
            int ul = warp * 4 + (rslot & 3);
            int gate = 2 * (rslot >> 3) + ((rslot >> 2) & 1);
            int R = gate * Ee + ul;
            float w0 = (kk < Hh) ? Wih[R * Hh + kk] : Whh[R * Ee + (kk - Hh)];
            float w1 = (kk + 1 < Hh) ? Wih[R * Hh + kk + 1] : Whh[R * Ee + (kk + 1 - Hh)];
            __half h0, l0, h1, l1;
            splith(w0, h0, l0);
            splith(w1, h1, l1);
            Ahi[kf][qq] = pkh(h0, h1);
            Alo[kf][qq] = pkh(l0, l1);
        }
    }

    const int u = warp * 4 + m;
    const int c = tg * 2 + q;
    const float bi_ = bih[u] + bhh[u];
    const float bf_ = bih[Ee + u] + bhh[Ee + u];
    const float bg_ = bih[2 * Ee + u] + bhh[2 * Ee + u];
    const float bo_ = bih[3 * Ee + u] + bhh[3 * Ee + u];

    char* bfb = (char*)&BF[0][0];
    const int cellOff = bf_off(c, Hh + u);               // h2 cell
    const int lk = tid & 127, lb = tid >> 7;
    const int lOff0 = bf_off(lb, lk);                    // h1 loader slots
    const int lOff1 = bf_off(lb + 4, lk);

    __syncthreads();   // zero done
    uint32_t p0 = g_seq1[((size_t)0 * Bb + r0 + lb) * Hh + lk];
    uint32_t p1 = g_seq1[((size_t)0 * Bb + r0 + lb + 4) * Hh + lk];
    *(__half*)(bfb + lOff0)     = __ushort_as_half((uint16_t)(p0 & 0xFFFF));
    *(__half*)(bfb + lOff0 + 8) = __ushort_as_half((uint16_t)(p0 >> 16));
    *(__half*)(bfb + lOff1)     = __ushort_as_half((uint16_t)(p1 & 0xFFFF));
    *(__half*)(bfb + lOff1 + 8) = __ushort_as_half((uint16_t)(p1 >> 16));
    p0 = g_seq1[((size_t)1 * Bb + r0 + lb) * Hh + lk];
    p1 = g_seq1[((size_t)1 * Bb + r0 + lb + 4) * Hh + lk];
    __syncthreads();

    float cst = 0.0f, hlast = 0.0f;
    const uint4* bfq = &BF[0][0] + (gid * 4 + tg);

    for (int t = 0; t < Tt; t++) {
        const int cur = t & 1;
        const uint4* bv = bfq + cur * BUF2;
        float dh[4] = {0.f,0.f,0.f,0.f}, dm[4] = {0.f,0.f,0.f,0.f}, dl[4] = {0.f,0.f,0.f,0.f};
#pragma unroll
        for (int kf = 0; kf < 12; kf++) {
            uint4 v = bv[kf * 32];
            mma16816(dh, Ahi[kf], v.x, v.y);
            mma16816(dm, Alo[kf], v.x, v.y);
            mma16816(dl, Ahi[kf], v.z, v.w);
        }
        float d0 = dh[0] + dm[0] + dl[0];
        float d1 = dh[1] + dm[1] + dl[1];
        float d2 = dh[2] + dm[2] + dl[2];
        float d3 = dh[3] + dm[3] + dl[3];

        float X = __shfl_xor_sync(0xFFFFFFFFu, q ? d0 : d1, 16);
        float Y = __shfl_xor_sync(0xFFFFFFFFu, q ? d2 : d3, 16);
        float zi = (q ? X : d0) + bi_;
        float zf = (q ? d1 : X) + bf_;
        float zg = (q ? Y : d2) + bg_;
        float zo = (q ? d3 : Y) + bo_;

        cst = sigm(zf) * cst + sigm(zi) * tanh_(zg);
        hlast = sigm(zo) * tanh_(cst);

        if (t + 1 < Tt) {
            const int nb = cur ^ 1;
            char* dst = bfb + nb * (int)sizeof(uint4) * BUF2;
            __half hh, hl;
            splith(hlast, hh, hl);
            *(__half*)(dst + cellOff) = hh;
            *(__half*)(dst + cellOff + 8) = hl;
            *(__half*)(dst + lOff0)     = __ushort_as_half((uint16_t)(p0 & 0xFFFF));
            *(__half*)(dst + lOff0 + 8) = __ushort_as_half((uint16_t)(p0 >> 16));
            *(__half*)(dst + lOff1)     = __ushort_as_half((uint16_t)(p1 & 0xFFFF));
            *(__half*)(dst + lOff1 + 8) = __ushort_as_half((uint16_t)(p1 >> 16));
            if (t + 2 < Tt) {
                p0 = g_seq1[((size_t)(t + 2) * Bb + r0 + lb) * Hh + lk];
                p1 = g_seq1[((size_t)(t + 2) * Bb + r0 + lb + 4) * Hh + lk];
            }
        }
        __syncthreads();
    }
    out[(size_t)(r0 + c) * Ee + u] = hlast;
}

extern "C" void kernel_launch(void* const* d_in, const int* in_sizes, int n_in,
                              void* d_out, int out_size)
{
    const float* x    = (const float*)d_in[0];
    const float* Wih1 = (const float*)d_in[1];
    const float* Whh1 = (const float*)d_in[2];
    const float* bih1 = (const float*)d_in[3];
    const float* bhh1 = (const float*)d_in[4];
    const float* Wih2 = (const float*)d_in[5];
    const float* Whh2 = (const float*)d_in[6];
    const float* bih2 = (const float*)d_in[7];
    const float* bhh2 = (const float*)d_in[8];
    float* out = (float*)d_out;

    lstm1_mma<<<128, 512>>>(x, Wih1, Whh1, bih1, bhh1);
    lstm2_mma<<<64, 512>>>(Wih2, Whh2, bih2, bhh2, out);
}

// round 14
// speedup vs baseline: 1.1709x; 1.0664x over previous
#include <cuda_runtime.h>
#include <cuda_fp16.h>
#include <cstdint>

#define Bb 512
#define Tt 512
#define Ff 32
#define Hh 128
#define Ee 64
#define NKF1 10            // lstm1 K-frags (K=160)
#define NKF2 12            // lstm2 K-frags (K=192)
#define BUF1 (NKF1*32)     // uint4s per buffer, lstm1 (5120 B)
#define BUF2 (NKF2*32)     // uint4s per buffer, lstm2 (6144 B)

__device__ uint32_t g_seq1[(size_t)Tt*Bb*Hh];   // layer-1 h packed (hi | lo<<16) fp16

// ---------------- helpers ----------------
__device__ __forceinline__ uint32_t smem_u32(const void* p) {
    uint32_t a;
    asm("{ .reg .u64 t; cvta.to.shared.u64 t, %1; cvt.u32.u64 %0, t; }" : "=r"(a) : "l"(p));
    return a;
}
__device__ __forceinline__ void mma16816(float* d, const uint32_t* a, uint32_t b0, uint32_t b1) {
    asm("mma.sync.aligned.m16n8k16.row.col.f32.f16.f16.f32 "
        "{%0,%1,%2,%3}, {%4,%5,%6,%7}, {%8,%9}, {%0,%1,%2,%3};"
        : "+f"(d[0]), "+f"(d[1]), "+f"(d[2]), "+f"(d[3])
        : "r"(a[0]), "r"(a[1]), "r"(a[2]), "r"(a[3]), "r"(b0), "r"(b1));
}
__device__ __forceinline__ void splith(float v, __half& hi, __half& lo) {
    hi = __float2half_rn(v);
    lo = __float2half_rn(v - __half2float(hi));
}
__device__ __forceinline__ uint32_t pkh(__half a, __half b) {
    return (uint32_t)__half_as_ushort(a) | ((uint32_t)__half_as_ushort(b) << 16);
}
// byte offset of value (n, k) inside a fragment-packed buffer.
__device__ __forceinline__ int bf_off(int n, int k) {
    int kf = k >> 4, r = k & 15;
    return ((kf * 8 + n) * 4 + ((r & 7) >> 1)) * 16 + (r >> 3) * 4 + (r & 1) * 2;
}
__device__ __forceinline__ void mbar_init(void* m, uint32_t cnt) {
    asm volatile("mbarrier.init.shared.b64 [%0], %1;" :: "r"(smem_u32(m)), "r"(cnt) : "memory");
}
__device__ __forceinline__ void mbar_wait(void* m, uint32_t parity) {
    uint32_t a = smem_u32(m), done;
    do {
        asm volatile("{\n\t.reg .pred p;\n\t"
            "mbarrier.try_wait.parity.acquire.cluster.shared::cta.b64 p, [%1], %2, 0x989680;\n\t"
            "selp.b32 %0, 1, 0, p;\n\t}" : "=r"(done) : "r"(a), "r"(parity) : "memory");
    } while (!done);
}
__device__ __forceinline__ uint32_t mapa_u32(uint32_t saddr, uint32_t peer) {
    uint32_t r;
    asm("mapa.shared::cluster.u32 %0, %1, %2;" : "=r"(r) : "r"(saddr), "r"(peer));
    return r;
}
#define CLU_SYNC() do { asm volatile("barrier.cluster.arrive.aligned;" ::: "memory"); \
                        asm volatile("barrier.cluster.wait.aligned;" ::: "memory"); } while (0)

// single-MUFU activations (tanh.approx.f32, sm_75+)
__device__ __forceinline__ float tanh_(float z) {
    float r;
    asm("tanh.approx.f32 %0, %1;" : "=f"(r) : "f"(z));
    return r;
}
__device__ __forceinline__ float sigm(float z) {
    return fmaf(tanh_(0.5f * z), 0.5f, 0.5f);
}

// ---------------------------------------------------------------------------
// Layer 1: 64 clusters x 2 CTAs x 512 threads (frag-packed B).
// CTA rank owns units U0..U0+63. K: 0..127 h (kf 0..7), 128..159 x (kf 8,9).
// Copier = warp 15 (no x-loader duty).
// ---------------------------------------------------------------------------
__global__ void __launch_bounds__(512, 1) __cluster_dims__(2, 1, 1)
lstm1_mma(const float* __restrict__ x,
          const float* __restrict__ Wih, const float* __restrict__ Whh,
          const float* __restrict__ bih, const float* __restrict__ bhh)
{
    __shared__ uint4 BF[2][BUF1];
    __shared__ alignas(8) unsigned long long mbar[2];

    const int tid = threadIdx.x;
    uint32_t rank;
    asm("mov.u32 %0, %%cluster_ctarank;" : "=r"(rank));
    const int r0 = (blockIdx.x >> 1) * 8;
    const int U0 = (int)rank * 64;
    const int lane = tid & 31, warp = tid >> 5;
    const int tg = lane & 3, gid = lane >> 2;
    const int q = gid >> 2, m = gid & 3;
    const int kf_own = (int)rank * 4;
    const int kf_peer = 4 - kf_own;

    for (int i = tid; i < 2 * BUF1; i += 512)
        ((uint4*)BF)[i] = make_uint4(0, 0, 0, 0);

    uint32_t Ahi[10][4], Alo[10][4];
#pragma unroll
    for (int kf = 0; kf < 10; kf++) {
        int k0 = kf * 16 + tg * 2;
#pragma unroll
        for (int qq = 0; qq < 4; qq++) {
            int rslot = gid + (qq & 1) * 8;
            int kk = k0 + (qq >> 1) * 8;
            int ul = warp * 4 + (rslot & 3);
            int gate = 2 * (rslot >> 3) + ((rslot >> 2) & 1);
            int R = gate * Hh + U0 + ul;
            float w0 = (kk < Hh) ? Whh[R * Hh + kk] : Wih[R * Ff + (kk - Hh)];
            float w1 = (kk + 1 < Hh) ? Whh[R * Hh + kk + 1] : Wih[R * Ff + (kk + 1 - Hh)];
            __half h0, l0, h1, l1;
            splith(w0, h0, l0);
            splith(w1, h1, l1);
            Ahi[kf][qq] = pkh(h0, h1);
            Alo[kf][qq] = pkh(l0, l1);
        }
    }

    const int u = U0 + warp * 4 + m;
    const int c = tg * 2 + q;
    const float bi_ = bih[u] + bhh[u];
    const float bf_ = bih[Hh + u] + bhh[Hh + u];
    const float bg_ = bih[2 * Hh + u] + bhh[2 * Hh + u];
    const float bo_ = bih[3 * Hh + u] + bhh[3 * Hh + u];

    if (tid == 0) { mbar_init(&mbar[0], 32); mbar_init(&mbar[1], 32); }
    __syncthreads();

    // copy warp = warp 15: own kf region = 4 kf x 512B = 2KB at rank*2048
    uint32_t cp_l = 0, cp_r = 0, rmb = 0;
    if (warp == 15) {
        cp_l = smem_u32(&BF[0][0]) + rank * 2048u + (uint32_t)lane * 16u;
        cp_r = mapa_u32(cp_l, rank ^ 1u);
        rmb  = mapa_u32(smem_u32(&mbar[0]), rank ^ 1u);
    }

    // per-thread precomputed fill offsets
    char* bfb = (char*)&BF[0][0];
    const int cellOff = bf_off(c, u);                    // own h cell
    const int xb = tid >> 5, xf = tid & 31;
    const int xOff = bf_off(xb, Hh + xf);                // x loader (tid<256)

    float xn = 0.0f;
    if (tid < 256) {
        float x0 = x[((size_t)(r0 + xb) * Tt + 0) * Ff + xf];
        __half xh, xl;
        splith(x0, xh, xl);
        *(__half*)(bfb + xOff) = xh;
        *(__half*)(bfb + xOff + 8) = xl;
        xn = x[((size_t)(r0 + xb) * Tt + 1) * Ff + xf];
    }
    __syncthreads();
    CLU_SYNC();

    float cst = 0.0f;
    int ph0 = 0, ph1 = 0;
    const uint4* bfq = &BF[0][0] + (gid * 4 + tg);       // + kf*32 per frag

    for (int t = 0; t < Tt; t++) {
        const int cur = t & 1;
        const uint4* bv = bfq + cur * BUF1;

        float dh[4] = {0.f,0.f,0.f,0.f}, dm[4] = {0.f,0.f,0.f,0.f}, dl[4] = {0.f,0.f,0.f,0.f};

        // local K-frags first: own units (4) + x (2)
#pragma unroll
        for (int i = 0; i < 6; i++) {
            const int kf = (i < 4) ? (kf_own + i) : (8 + (i - 4));
            uint4 v = bv[kf * 32];
            mma16816(dh, Ahi[kf], v.x, v.y);
            mma16816(dm, Alo[kf], v.x, v.y);
            mma16816(dl, Ahi[kf], v.z, v.w);
        }

        if (t > 0) {
            if (cur == 0) { mbar_wait(&mbar[0], (uint32_t)ph0); ph0 ^= 1; }
            else          { mbar_wait(&mbar[1], (uint32_t)ph1); ph1 ^= 1; }
        }
#pragma unroll
        for (int i = 0; i < 4; i++) {
            const int kf = kf_peer + i;
            uint4 v = bv[kf * 32];
            mma16816(dh, Ahi[kf], v.x, v.y);
            mma16816(dm, Alo[kf], v.x, v.y);
            mma16816(dl, Ahi[kf], v.z, v.w);
        }

        float d0 = dh[0] + dm[0] + dl[0];
        float d1 = dh[1] + dm[1] + dl[1];
        float d2 = dh[2] + dm[2] + dl[2];
        float d3 = dh[3] + dm[3] + dl[3];

        float X = __shfl_xor_sync(0xFFFFFFFFu, q ? d0 : d1, 16);
        float Y = __shfl_xor_sync(0xFFFFFFFFu, q ? d2 : d3, 16);
        float zi = (q ? X : d0) + bi_;
        float zf = (q ? d1 : X) + bf_;
        float zg = (q ? Y : d2) + bg_;
        float zo = (q ? d3 : Y) + bo_;

        cst = sigm(zf) * cst + sigm(zi) * tanh_(zg);
        float h = sigm(zo) * tanh_(cst);
        __half hh, hl;
        splith(h, hh, hl);
        g_seq1[((size_t)t * Bb + r0 + c) * Hh + u] = pkh(hh, hl);

        const int nb = cur ^ 1;
        if (t + 1 < Tt) {
            char* dst = bfb + nb * (int)sizeof(uint4) * BUF1;
            *(__half*)(dst + cellOff) = hh;
            *(__half*)(dst + cellOff + 8) = hl;
            if (tid < 256) {
                __half xh, xl;
                splith(xn, xh, xl);
                *(__half*)(dst + xOff) = xh;
                *(__half*)(dst + xOff + 8) = xl;
                xn = (t + 2 < Tt) ? x[((size_t)(r0 + xb) * Tt + t + 2) * Ff + xf] : 0.0f;
            }
        }
        __syncthreads();

        if (t + 1 < Tt && warp == 15) {
            const uint32_t bofs = (uint32_t)nb * (uint32_t)(sizeof(uint4) * BUF1);
#pragma unroll
            for (int j = 0; j < 4; j++) {
                uint32_t la = cp_l + bofs + (uint32_t)j * 512u;
                uint32_t ra = cp_r + bofs + (uint32_t)j * 512u;
                uint32_t v0, v1, v2, v3;
                asm volatile("ld.shared.v4.u32 {%0,%1,%2,%3}, [%4];"
                    : "=r"(v0), "=r"(v1), "=r"(v2), "=r"(v3) : "r"(la));
                unsigned long long p0, p1;
                asm("mov.b64 %0, {%1, %2};" : "=l"(p0) : "r"(v0), "r"(v1));
                asm("mov.b64 %0, {%1, %2};" : "=l"(p1) : "r"(v2), "r"(v3));
                asm volatile("st.shared::cluster.b64 [%0], %1;" :: "r"(ra), "l"(p0) : "memory");
                asm volatile("st.shared::cluster.b64 [%0], %1;" :: "r"(ra + 8), "l"(p1) : "memory");
            }
            asm volatile("mbarrier.arrive.release.cluster.shared::cluster.b64 _, [%0];"
                :: "r"(rmb + (uint32_t)nb * 8) : "memory");
        }
    }
    CLU_SYNC();
}

// ---------------------------------------------------------------------------
// Layer 2: 64 blocks x 512 threads (frag-packed B).
// K: 0..127 h1 (kf 0..7), 128..191 h2 (kf 8..11).
// ---------------------------------------------------------------------------
__global__ void __launch_bounds__(512, 1)
lstm2_mma(const float* __restrict__ Wih, const float* __restrict__ Whh,
          const float* __restrict__ bih, const float* __restrict__ bhh,
          float* __restrict__ out)
{
    __shared__ uint4 BF[2][BUF2];

    const int tid = threadIdx.x;
    const int r0 = blockIdx.x * 8;
    const int lane = tid & 31, warp = tid >> 5;
    const int tg = lane & 3, gid = lane >> 2;
    const int q = gid >> 2, m = gid & 3;

    for (int i = tid; i < 2 * BUF2; i += 512)
        ((uint4*)BF)[i] = make_uint4(0, 0, 0, 0);

    uint32_t Ahi[12][4], Alo[12][4];
#pragma unroll
    for (int kf = 0; kf < 12; kf++) {
        int k0 = kf * 16 + tg * 2;
#pragma unroll
        for (int qq = 0; qq < 4; qq++) {
            int rslot = gid + (qq & 1) * 8;
            int kk = k0 + (qq >> 1) * 8;
            int ul = warp * 4 + (rslot & 3);
            int gate = 2 * (rslot >> 3) + ((rslot >> 2) & 1);
            int R = gate * Ee + ul;
            float w0 = (kk < Hh) ? Wih[R * Hh + kk] : Whh[R * Ee + (kk - Hh)];
            float w1 = (kk + 1 < Hh) ? Wih[R * Hh + kk + 1] : Whh[R * Ee + (kk + 1 - Hh)];
            __half h0, l0, h1, l1;
            splith(w0, h0, l0);
            splith(w1, h1, l1);
            Ahi[kf][qq] = pkh(h0, h1);
            Alo[kf][qq] = pkh(l0, l1);
        }
    }

    const int u = warp * 4 + m;
    const int c = tg * 2 + q;
    const float bi_ = bih[u] + bhh[u];
    const float bf_ = bih[Ee + u] + bhh[Ee + u];
    const float bg_ = bih[2 * Ee + u] + bhh[2 * Ee + u];
    const float bo_ = bih[3 * Ee + u] + bhh[3 * Ee + u];

    char* bfb = (char*)&BF[0][0];
    const int cellOff = bf_off(c, Hh + u);               // h2 cell
    const int lk = tid & 127, lb = tid >> 7;
    const int lOff0 = bf_off(lb, lk);                    // h1 loader slots
    const int lOff1 = bf_off(lb + 4, lk);

    __syncthreads();   // zero done
    uint32_t p0 = g_seq1[((size_t)0 * Bb + r0 + lb) * Hh + lk];
    uint32_t p1 = g_seq1[((size_t)0 * Bb + r0 + lb + 4) * Hh + lk];
    *(__half*)(bfb + lOff0)     = __ushort_as_half((uint16_t)(p0 & 0xFFFF));
    *(__half*)(bfb + lOff0 + 8) = __ushort_as_half((uint16_t)(p0 >> 16));
    *(__half*)(bfb + lOff1)     = __ushort_as_half((uint16_t)(p1 & 0xFFFF));
    *(__half*)(bfb + lOff1 + 8) = __ushort_as_half((uint16_t)(p1 >> 16));
    p0 = g_seq1[((size_t)1 * Bb + r0 + lb) * Hh + lk];
    p1 = g_seq1[((size_t)1 * Bb + r0 + lb + 4) * Hh + lk];
    __syncthreads();

    float cst = 0.0f, hlast = 0.0f;
    const uint4* bfq = &BF[0][0] + (gid * 4 + tg);

    for (int t = 0; t < Tt; t++) {
        const int cur = t & 1;
        const uint4* bv = bfq + cur * BUF2;
        float dh[4] = {0.f,0.f,0.f,0.f}, dm[4] = {0.f,0.f,0.f,0.f}, dl[4] = {0.f,0.f,0.f,0.f};
#pragma unroll
        for (int kf = 0; kf < 12; kf++) {
            uint4 v = bv[kf * 32];
            mma16816(dh, Ahi[kf], v.x, v.y);
            mma16816(dm, Alo[kf], v.x, v.y);
            mma16816(dl, Ahi[kf], v.z, v.w);
        }
        float d0 = dh[0] + dm[0] + dl[0];
        float d1 = dh[1] + dm[1] + dl[1];
        float d2 = dh[2] + dm[2] + dl[2];
        float d3 = dh[3] + dm[3] + dl[3];

        float X = __shfl_xor_sync(0xFFFFFFFFu, q ? d0 : d1, 16);
        float Y = __shfl_xor_sync(0xFFFFFFFFu, q ? d2 : d3, 16);
        float zi = (q ? X : d0) + bi_;
        float zf = (q ? d1 : X) + bf_;
        float zg = (q ? Y : d2) + bg_;
        float zo = (q ? d3 : Y) + bo_;

        cst = sigm(zf) * cst + sigm(zi) * tanh_(zg);
        hlast = sigm(zo) * tanh_(cst);

        if (t + 1 < Tt) {
            const int nb = cur ^ 1;
            char* dst = bfb + nb * (int)sizeof(uint4) * BUF2;
            __half hh, hl;
            splith(hlast, hh, hl);
            *(__half*)(dst + cellOff) = hh;
            *(__half*)(dst + cellOff + 8) = hl;
            *(__half*)(dst + lOff0)     = __ushort_as_half((uint16_t)(p0 & 0xFFFF));
            *(__half*)(dst + lOff0 + 8) = __ushort_as_half((uint16_t)(p0 >> 16));
            *(__half*)(dst + lOff1)     = __ushort_as_half((uint16_t)(p1 & 0xFFFF));
            *(__half*)(dst + lOff1 + 8) = __ushort_as_half((uint16_t)(p1 >> 16));
            if (t + 2 < Tt) {
                p0 = g_seq1[((size_t)(t + 2) * Bb + r0 + lb) * Hh + lk];
                p1 = g_seq1[((size_t)(t + 2) * Bb + r0 + lb + 4) * Hh + lk];
            }
        }
        __syncthreads();
    }
    out[(size_t)(r0 + c) * Ee + u] = hlast;
}

extern "C" void kernel_launch(void* const* d_in, const int* in_sizes, int n_in,
                              void* d_out, int out_size)
{
    const float* x    = (const float*)d_in[0];
    const float* Wih1 = (const float*)d_in[1];
    const float* Whh1 = (const float*)d_in[2];
    const float* bih1 = (const float*)d_in[3];
    const float* bhh1 = (const float*)d_in[4];
    const float* Wih2 = (const float*)d_in[5];
    const float* Whh2 = (const float*)d_in[6];
    const float* bih2 = (const float*)d_in[7];
    const float* bhh2 = (const float*)d_in[8];
    float* out = (float*)d_out;

    lstm1_mma<<<128, 512>>>(x, Wih1, Whh1, bih1, bhh1);
    lstm2_mma<<<64, 512>>>(Wih2, Whh2, bih2, bhh2, out);
}

// round 15
// speedup vs baseline: 1.9183x; 1.6382x over previous
#include <cuda_runtime.h>
#include <cuda_fp16.h>
#include <cstdint>

#define Bb 512
#define Tt 512
#define Ff 32
#define Hh 128
#define Ee 64

// producer (layer1) smem: WS = lo-weight frags [16 warps][20 slots][32 lanes] uint4
#define WS_U4   (16*20*32)            // 10240 uint4 = 163840 B
#define BUF1R   (10*32)               // 320 uint4 per B buffer (10 kf)
#define DYN_BYTES ((WS_U4 + 2*BUF1R)*16)   // 174080
// consumer (layer2) B buffers
#define NKF2 12
#define BUF2 (NKF2*32)                // 384 uint4 per buffer

__device__ uint32_t g_seq1[(size_t)Tt*Bb*Hh];   // layer-1 h packed (hi | lo<<16) fp16
__device__ int g_flag[64];                      // per batch-group completed-step count

// ---------------- helpers ----------------
__device__ __forceinline__ uint32_t smem_u32(const void* p) {
    uint32_t a;
    asm("{ .reg .u64 t; cvta.to.shared.u64 t, %1; cvt.u32.u64 %0, t; }" : "=r"(a) : "l"(p));
    return a;
}
__device__ __forceinline__ void mma16816(float* d, const uint32_t* a, uint32_t b0, uint32_t b1) {
    asm("mma.sync.aligned.m16n8k16.row.col.f32.f16.f16.f32 "
        "{%0,%1,%2,%3}, {%4,%5,%6,%7}, {%8,%9}, {%0,%1,%2,%3};"
        : "+f"(d[0]), "+f"(d[1]), "+f"(d[2]), "+f"(d[3])
        : "r"(a[0]), "r"(a[1]), "r"(a[2]), "r"(a[3]), "r"(b0), "r"(b1));
}
__device__ __forceinline__ void splith(float v, __half& hi, __half& lo) {
    hi = __float2half_rn(v);
    lo = __float2half_rn(v - __half2float(hi));
}
__device__ __forceinline__ uint32_t pkh(__half a, __half b) {
    return (uint32_t)__half_as_ushort(a) | ((uint32_t)__half_as_ushort(b) << 16);
}
// byte offset of value (n, k) inside a fragment-packed buffer
__device__ __forceinline__ int bf_off(int n, int k) {
    int kf = k >> 4, r = k & 15;
    return ((kf * 8 + n) * 4 + ((r & 7) >> 1)) * 16 + (r >> 3) * 4 + (r & 1) * 2;
}
__device__ __forceinline__ void st_release(int* p, int v) {
    asm volatile("st.release.gpu.s32 [%0], %1;" :: "l"(p), "r"(v) : "memory");
}
__device__ __forceinline__ int ld_acquire(const int* p) {
    int v;
    asm volatile("ld.acquire.gpu.s32 %0, [%1];" : "=r"(v) : "l"(p) : "memory");
    return v;
}
__device__ __forceinline__ void wait_flag(const int* p, int need) {
    while (ld_acquire(p) < need) { }
}
// single-MUFU activations
__device__ __forceinline__ float tanh_(float z) {
    float r;
    asm("tanh.approx.f32 %0, %1;" : "=f"(r) : "f"(z));
    return r;
}
__device__ __forceinline__ float sigm(float z) {
    return fmaf(tanh_(0.5f * z), 0.5f, 0.5f);
}

__global__ void flags_reset_k() {
    if (threadIdx.x < 64) g_flag[threadIdx.x] = 0;
}

// ---------------------------------------------------------------------------
// Fused: CTAs 0..63 = layer-1 producers (8 batch, ALL 512 gates, no cluster);
//        CTAs 64..127 = layer-2 consumers (8 batch), gated by g_flag.
// ---------------------------------------------------------------------------
__global__ void __launch_bounds__(512, 1)
fused_lstm(const float* __restrict__ x,
           const float* __restrict__ Wih1, const float* __restrict__ Whh1,
           const float* __restrict__ bih1, const float* __restrict__ bhh1,
           const float* __restrict__ Wih2, const float* __restrict__ Whh2,
           const float* __restrict__ bih2, const float* __restrict__ bhh2,
           float* __restrict__ out)
{
    extern __shared__ uint4 dyn[];
    const int tid = threadIdx.x;
    const int lane = tid & 31, warp = tid >> 5;
    const int tg = lane & 3, gid = lane >> 2;

    if (blockIdx.x < 64) {
        // ===================== LAYER-1 PRODUCER =====================
        uint4* WS = dyn;                    // lo-weight frags
        uint4* BF = dyn + WS_U4;            // 2 x BUF1R activation buffers
        char*  bfb = (char*)BF;
        const int r0 = blockIdx.x * 8;
        const int u = warp * 8 + gid;       // this thread's hidden unit

        // zero B buffers
        for (int i = tid; i < 2 * BUF1R; i += 512) BF[i] = make_uint4(0, 0, 0, 0);

        // weights: hi in regs (Ahi[kf*2+rt]), lo into WS
        uint32_t Ahi[20][4];
#pragma unroll
        for (int kf = 0; kf < 10; kf++) {
            int k0 = kf * 16 + tg * 2;
#pragma unroll
            for (int rt = 0; rt < 2; rt++) {
                uint32_t lo4[4];
#pragma unroll
                for (int qq = 0; qq < 4; qq++) {
                    int hp = qq & 1;
                    int kk = k0 + (qq >> 1) * 8;
                    int gate = 2 * rt + hp;
                    int R = gate * Hh + u;
                    float w0 = (kk < Hh) ? Whh1[R * Hh + kk] : Wih1[R * Ff + (kk - Hh)];
                    float w1 = (kk + 1 < Hh) ? Whh1[R * Hh + kk + 1] : Wih1[R * Ff + (kk + 1 - Hh)];
                    __half h0, l0, h1, l1;
                    splith(w0, h0, l0);
                    splith(w1, h1, l1);
                    Ahi[kf * 2 + rt][qq] = pkh(h0, h1);
                    lo4[qq] = pkh(l0, l1);
                }
                WS[((warp * 20 + kf * 2 + rt) * 32 + lane)] =
                    make_uint4(lo4[0], lo4[1], lo4[2], lo4[3]);
            }
        }

        const float bi_ = bih1[u] + bhh1[u];
        const float bf_ = bih1[Hh + u] + bhh1[Hh + u];
        const float bg_ = bih1[2 * Hh + u] + bhh1[2 * Hh + u];
        const float bo_ = bih1[3 * Hh + u] + bhh1[3 * Hh + u];

        const int bA = 2 * tg, bB = 2 * tg + 1;     // this thread's 2 batch cols
        const int offA = bf_off(bA, u), offB = bf_off(bB, u);

        // x loaders: tid<256 -> (batch xb 0..7, feature xf 0..31)
        const int xb = tid >> 5, xf = tid & 31;
        const int xOff = bf_off(xb, Hh + xf);
        float xn = 0.0f;
        if (tid < 256) {
            float x0 = x[((size_t)(r0 + xb) * Tt + 0) * Ff + xf];
            __half xh, xl;
            splith(x0, xh, xl);
            *(__half*)(bfb + xOff) = xh;
            *(__half*)(bfb + xOff + 8) = xl;
            xn = x[((size_t)(r0 + xb) * Tt + 1) * Ff + xf];
        }
        __syncthreads();

        float cstA = 0.0f, cstB = 0.0f;
        const uint4* bfq = BF + (gid * 4 + tg);
        const uint4* wsp = WS + (warp * 20) * 32 + lane;

        for (int t = 0; t < Tt; t++) {
            const int cur = t & 1, nb = cur ^ 1;
            const uint4* bv = bfq + cur * BUF1R;

            float d0[4] = {0.f, 0.f, 0.f, 0.f};
            float d1[4] = {0.f, 0.f, 0.f, 0.f};
#pragma unroll
            for (int kf = 0; kf < 10; kf++) {
                uint4 v  = bv[kf * 32];
                uint4 l0 = wsp[(kf * 2 + 0) * 32];
                uint4 l1 = wsp[(kf * 2 + 1) * 32];
                mma16816(d0, Ahi[kf * 2 + 0], v.x, v.y);
                mma16816(d1, Ahi[kf * 2 + 1], v.x, v.y);
                mma16816(d0, (const uint32_t*)&l0, v.x, v.y);
                mma16816(d1, (const uint32_t*)&l1, v.x, v.y);
                mma16816(d0, Ahi[kf * 2 + 0], v.z, v.w);
                mma16816(d1, Ahi[kf * 2 + 1], v.z, v.w);
            }

            // cell A (batch bA): gates i,f from tile0 rows gid/gid+8; g,o from tile1
            float ziA = d0[0] + bi_, zfA = d0[2] + bf_;
            float zgA = d1[0] + bg_, zoA = d1[2] + bo_;
            cstA = sigm(zfA) * cstA + sigm(ziA) * tanh_(zgA);
            float hA = sigm(zoA) * tanh_(cstA);
            // cell B (batch bB)
            float ziB = d0[1] + bi_, zfB = d0[3] + bf_;
            float zgB = d1[1] + bg_, zoB = d1[3] + bo_;
            cstB = sigm(zfB) * cstB + sigm(ziB) * tanh_(zgB);
            float hB = sigm(zoB) * tanh_(cstB);

            __half hAh, hAl, hBh, hBl;
            splith(hA, hAh, hAl);
            splith(hB, hBh, hBl);
            g_seq1[((size_t)t * Bb + r0 + bA) * Hh + u] = pkh(hAh, hAl);
            g_seq1[((size_t)t * Bb + r0 + bB) * Hh + u] = pkh(hBh, hBl);

            if (t + 1 < Tt) {
                char* dst = bfb + nb * (BUF1R * 16);
                *(__half*)(dst + offA) = hAh;
                *(__half*)(dst + offA + 8) = hAl;
                *(__half*)(dst + offB) = hBh;
                *(__half*)(dst + offB + 8) = hBl;
                if (tid < 256) {
                    __half xh, xl;
                    splith(xn, xh, xl);
                    *(__half*)(dst + xOff) = xh;
                    *(__half*)(dst + xOff + 8) = xl;
                    xn = (t + 2 < Tt) ? x[((size_t)(r0 + xb) * Tt + t + 2) * Ff + xf] : 0.0f;
                }
            }
            __syncthreads();
            if (tid == 0) st_release(&g_flag[blockIdx.x], t + 1);
        }
    } else {
        // ===================== LAYER-2 CONSUMER (R14 lstm2 + flag gating) =====================
        uint4* BF2 = dyn;                   // 2 x BUF2
        char*  bfb = (char*)BF2;
        const int bg = blockIdx.x - 64;
        const int r0 = bg * 8;
        const int* flag = &g_flag[bg];
        const int q = gid >> 2, m = gid & 3;

        for (int i = tid; i < 2 * BUF2; i += 512) BF2[i] = make_uint4(0, 0, 0, 0);

        uint32_t Ahi[12][4], Alo[12][4];
#pragma unroll
        for (int kf = 0; kf < 12; kf++) {
            int k0 = kf * 16 + tg * 2;
#pragma unroll
            for (int qq = 0; qq < 4; qq++) {
                int rslot = gid + (qq & 1) * 8;
                int kk = k0 + (qq >> 1) * 8;
                int ul = warp * 4 + (rslot & 3);
                int gate = 2 * (rslot >> 3) + ((rslot >> 2) & 1);
                int R = gate * Ee + ul;
                float w0 = (kk < Hh) ? Wih2[R * Hh + kk] : Whh2[R * Ee + (kk - Hh)];
                float w1 = (kk + 1 < Hh) ? Wih2[R * Hh + kk + 1] : Whh2[R * Ee + (kk + 1 - Hh)];
                __half h0, l0, h1, l1;
                splith(w0, h0, l0);
                splith(w1, h1, l1);
                Ahi[kf][qq] = pkh(h0, h1);
                Alo[kf][qq] = pkh(l0, l1);
            }
        }

        const int u = warp * 4 + m;
        const int c = tg * 2 + q;
        const float bi_ = bih2[u] + bhh2[u];
        const float bf_ = bih2[Ee + u] + bhh2[Ee + u];
        const float bg_ = bih2[2 * Ee + u] + bhh2[2 * Ee + u];
        const float bo_ = bih2[3 * Ee + u] + bhh2[3 * Ee + u];

        const int cellOff = bf_off(c, Hh + u);
        const int lk = tid & 127, lb = tid >> 7;
        const int lOff0 = bf_off(lb, lk);
        const int lOff1 = bf_off(lb + 4, lk);

        __syncthreads();   // zero done
        wait_flag(flag, 2);   // seq1[0], seq1[1] available
        uint32_t p0 = g_seq1[((size_t)0 * Bb + r0 + lb) * Hh + lk];
        uint32_t p1 = g_seq1[((size_t)0 * Bb + r0 + lb + 4) * Hh + lk];
        *(__half*)(bfb + lOff0)     = __ushort_as_half((uint16_t)(p0 & 0xFFFF));
        *(__half*)(bfb + lOff0 + 8) = __ushort_as_half((uint16_t)(p0 >> 16));
        *(__half*)(bfb + lOff1)     = __ushort_as_half((uint16_t)(p1 & 0xFFFF));
        *(__half*)(bfb + lOff1 + 8) = __ushort_as_half((uint16_t)(p1 >> 16));
        p0 = g_seq1[((size_t)1 * Bb + r0 + lb) * Hh + lk];
        p1 = g_seq1[((size_t)1 * Bb + r0 + lb + 4) * Hh + lk];
        __syncthreads();

        float cst = 0.0f, hlast = 0.0f;
        const uint4* bfq = BF2 + (gid * 4 + tg);

        for (int t = 0; t < Tt; t++) {
            const int cur = t & 1;
            const uint4* bv = bfq + cur * BUF2;
            float dh[4] = {0.f,0.f,0.f,0.f}, dm[4] = {0.f,0.f,0.f,0.f}, dl[4] = {0.f,0.f,0.f,0.f};
#pragma unroll
            for (int kf = 0; kf < 12; kf++) {
                uint4 v = bv[kf * 32];
                mma16816(dh, Ahi[kf], v.x, v.y);
                mma16816(dm, Alo[kf], v.x, v.y);
                mma16816(dl, Ahi[kf], v.z, v.w);
            }
            float d0 = dh[0] + dm[0] + dl[0];
            float d1 = dh[1] + dm[1] + dl[1];
            float d2 = dh[2] + dm[2] + dl[2];
            float d3 = dh[3] + dm[3] + dl[3];

            float X = __shfl_xor_sync(0xFFFFFFFFu, q ? d0 : d1, 16);
            float Y = __shfl_xor_sync(0xFFFFFFFFu, q ? d2 : d3, 16);
            float zi = (q ? X : d0) + bi_;
            float zf = (q ? d1 : X) + bf_;
            float zg = (q ? Y : d2) + bg_;
            float zo = (q ? d3 : Y) + bo_;

            cst = sigm(zf) * cst + sigm(zi) * tanh_(zg);
            hlast = sigm(zo) * tanh_(cst);

            if (t + 1 < Tt) {
                const int nb = cur ^ 1;
                char* dst = bfb + nb * (BUF2 * 16);
                __half hh, hl;
                splith(hlast, hh, hl);
                *(__half*)(dst + cellOff) = hh;
                *(__half*)(dst + cellOff + 8) = hl;
                *(__half*)(dst + lOff0)     = __ushort_as_half((uint16_t)(p0 & 0xFFFF));
                *(__half*)(dst + lOff0 + 8) = __ushort_as_half((uint16_t)(p0 >> 16));
                *(__half*)(dst + lOff1)     = __ushort_as_half((uint16_t)(p1 & 0xFFFF));
                *(__half*)(dst + lOff1 + 8) = __ushort_as_half((uint16_t)(p1 >> 16));
                if (t + 2 < Tt) {
                    wait_flag(flag, t + 3);   // seq1[t+2] published
                    p0 = g_seq1[((size_t)(t + 2) * Bb + r0 + lb) * Hh + lk];
                    p1 = g_seq1[((size_t)(t + 2) * Bb + r0 + lb + 4) * Hh + lk];
                }
            }
            __syncthreads();
        }
        out[(size_t)(r0 + c) * Ee + u] = hlast;
    }
}

extern "C" void kernel_launch(void* const* d_in, const int* in_sizes, int n_in,
                              void* d_out, int out_size)
{
    const float* x    = (const float*)d_in[0];
    const float* Wih1 = (const float*)d_in[1];
    const float* Whh1 = (const float*)d_in[2];
    const float* bih1 = (const float*)d_in[3];
    const float* bhh1 = (const float*)d_in[4];
    const float* Wih2 = (const float*)d_in[5];
    const float* Whh2 = (const float*)d_in[6];
    const float* bih2 = (const float*)d_in[7];
    const float* bhh2 = (const float*)d_in[8];
    float* out = (float*)d_out;

    cudaFuncSetAttribute(fused_lstm, cudaFuncAttributeMaxDynamicSharedMemorySize, DYN_BYTES);

    flags_reset_k<<<1, 64>>>();
    fused_lstm<<<128, 512, DYN_BYTES>>>(x, Wih1, Whh1, bih1, bhh1,
                                        Wih2, Whh2, bih2, bhh2, out);
}